// round 1
// baseline (speedup 1.0000x reference)
#include <cuda_runtime.h>
#include <cuda_bf16.h>
#include <math.h>

#define N_ENT  50000
#define N_EDGE 500000
#define H      128
#define N_REL  475

// -------- scratch (static __device__ — no allocation allowed) --------
__device__ float g_ex[3][N_EDGE];        // exp(logit) per layer per edge (6 MB)
__device__ float g_sum[3][N_ENT];        // softmax denominators            (600 KB)
__device__ float g_neigh[3][N_ENT * H];  // aggregated neighborhoods        (76.8 MB)

// 16B vectorized no-return global reduction (sm_90+)
__device__ __forceinline__ void red4(float* p, float4 v) {
    asm volatile("red.global.add.v4.f32 [%0], {%1,%2,%3,%4};"
                 :: "l"(p), "f"(v.x), "f"(v.y), "f"(v.z), "f"(v.w)
                 : "memory");
}

// -------- K0: zero sums + neigh, copy ent -> out --------
__global__ void k_init(const float* __restrict__ ent, float* __restrict__ out) {
    int i = blockIdx.x * blockDim.x + threadIdx.x;   // grid covers 3*N_ENT*H exactly
    ((float*)g_neigh)[i] = 0.0f;
    if (i < N_ENT * H) out[i] = ent[i];
    if (i < 3 * N_ENT) ((float*)g_sum)[i] = 0.0f;
}

// -------- K1: per-edge logits -> exp -> atomic denominator sums --------
// One warp per edge. All gathers hit L2 (tables fit).
__global__ void k_logits(const float* __restrict__ ent, const float* __restrict__ rel,
                         const int* __restrict__ src, const int* __restrict__ dst,
                         const int* __restrict__ rid) {
    int e    = (blockIdx.x * blockDim.x + threadIdx.x) >> 5;
    int lane = threadIdx.x & 31;
    if (e >= N_EDGE) return;
    int s = src[e], d = dst[e], r = rid[e];

    float4 u = ((const float4*)(ent + (size_t)s * H))[lane];
    float4 v = ((const float4*)(ent + (size_t)d * H))[lane];
    float4 q = ((const float4*)(rel + (size_t)r * H))[lane];

    float ln = u.x * v.x + u.y * v.y + u.z * v.z + u.w * v.w;  // dot(u, v)
    float le = q.x * v.x + q.y * v.y + q.z * v.z + q.w * v.w;  // dot(r, v)
    #pragma unroll
    for (int o = 16; o; o >>= 1) {
        ln += __shfl_xor_sync(0xffffffffu, ln, o);
        le += __shfl_xor_sync(0xffffffffu, le, o);
    }
    if (lane == 0) {
        // softmax is shift-invariant; |logit| <~ 0.5 so exp() without max is exact
        float ee = __expf(le);
        float en = __expf(ln);
        float ec = __expf(le + ln);
        g_ex[0][e] = ee;  g_ex[1][e] = en;  g_ex[2][e] = ec;
        atomicAdd(&g_sum[0][d], ee);
        atomicAdd(&g_sum[1][d], en);
        atomicAdd(&g_sum[2][d], ec);
    }
}

// -------- K2: per-edge weighted scatter into g_neigh (vector red) --------
__global__ void k_scatter(const float* __restrict__ ent, const float* __restrict__ rel,
                          const int* __restrict__ src, const int* __restrict__ dst,
                          const int* __restrict__ rid) {
    int e    = (blockIdx.x * blockDim.x + threadIdx.x) >> 5;
    int lane = threadIdx.x & 31;
    if (e >= N_EDGE) return;
    int s = src[e], d = dst[e], r = rid[e];

    float ae = __fdividef(g_ex[0][e], g_sum[0][d]);
    float an = __fdividef(g_ex[1][e], g_sum[1][d]);
    float ac = __fdividef(g_ex[2][e], g_sum[2][d]);

    float4 u = ((const float4*)(ent + (size_t)s * H))[lane];
    float4 q = ((const float4*)(rel + (size_t)r * H))[lane];

    size_t off = (size_t)d * H + lane * 4;
    red4(&g_neigh[0][off], make_float4(q.x * ae, q.y * ae, q.z * ae, q.w * ae));
    red4(&g_neigh[1][off], make_float4(u.x * an, u.y * an, u.z * an, u.w * an));
    red4(&g_neigh[2][off], make_float4((u.x + q.x) * ac, (u.y + q.y) * ac,
                                       (u.z + q.z) * ac, (u.w + q.w) * ac));
}

// -------- K3: out += tanh(neigh @ W), one launch per layer --------
// Block tile 128x128, 256 threads (16x16), 8x8 register tile per thread.
__global__ void __launch_bounds__(256, 2)
k_gemm(int layer, const float* __restrict__ W, float* __restrict__ out) {
    const float* neigh = g_neigh[layer];
    __shared__ float sN[128][16];   // [n][k] — a-reads are ty-only -> broadcast
    __shared__ float sW[16][128];   // [k][h]

    int tx = threadIdx.x & 15;      // h-tile index
    int ty = threadIdx.x >> 4;      // n-tile index
    int row0 = blockIdx.x * 128;

    float acc[8][8];
    #pragma unroll
    for (int i = 0; i < 8; i++)
        #pragma unroll
        for (int j = 0; j < 8; j++) acc[i][j] = 0.0f;

    for (int k0 = 0; k0 < H; k0 += 16) {
        int t = threadIdx.x;
        // load sN: 128 rows x 16 cols = 512 float4, 2 per thread (coalesced)
        #pragma unroll
        for (int i = 0; i < 2; i++) {
            int idx = t + i * 256;          // 0..511
            int n   = idx >> 2;             // 0..127
            int kq  = (idx & 3) * 4;        // 0,4,8,12
            float4 val = (row0 + n < N_ENT)
                ? *(const float4*)(neigh + (size_t)(row0 + n) * H + k0 + kq)
                : make_float4(0.f, 0.f, 0.f, 0.f);
            *(float4*)&sN[n][kq] = val;
        }
        // load sW: 16 rows x 128 cols = 512 float4, 2 per thread
        #pragma unroll
        for (int i = 0; i < 2; i++) {
            int idx = t + i * 256;
            int kk  = idx >> 5;             // 0..15
            int h4  = (idx & 31) * 4;
            *(float4*)&sW[kk][h4] = *(const float4*)(W + (size_t)(k0 + kk) * H + h4);
        }
        __syncthreads();
        #pragma unroll
        for (int kk = 0; kk < 16; kk++) {
            float a[8], b[8];
            #pragma unroll
            for (int i = 0; i < 8; i++) a[i] = sN[ty * 8 + i][kk];
            float4 b0 = *(float4*)&sW[kk][tx * 8];
            float4 b1 = *(float4*)&sW[kk][tx * 8 + 4];
            b[0]=b0.x; b[1]=b0.y; b[2]=b0.z; b[3]=b0.w;
            b[4]=b1.x; b[5]=b1.y; b[6]=b1.z; b[7]=b1.w;
            #pragma unroll
            for (int i = 0; i < 8; i++)
                #pragma unroll
                for (int j = 0; j < 8; j++) acc[i][j] += a[i] * b[j];
        }
        __syncthreads();
    }

    #pragma unroll
    for (int i = 0; i < 8; i++) {
        int n = row0 + ty * 8 + i;
        if (n < N_ENT) {
            #pragma unroll
            for (int j = 0; j < 8; j++)
                out[(size_t)n * H + tx * 8 + j] += tanhf(acc[i][j]);
        }
    }
}

extern "C" void kernel_launch(void* const* d_in, const int* in_sizes, int n_in,
                              void* d_out, int out_size) {
    const float* ent    = (const float*)d_in[0];
    const float* rel    = (const float*)d_in[1];
    const float* w_edge = (const float*)d_in[2];
    const float* w_node = (const float*)d_in[3];
    const float* w_comp = (const float*)d_in[4];
    const int*   src    = (const int*)d_in[5];
    const int*   dst    = (const int*)d_in[6];
    const int*   rid    = (const int*)d_in[7];
    float*       out    = (float*)d_out;

    // 3*N_ENT*H = 19,200,000 = 75000 * 256 exactly
    k_init<<<(3 * N_ENT * H) / 256, 256>>>(ent, out);
    // N_EDGE warps = 500000; 8 warps/block -> 62500 blocks exactly
    k_logits <<<N_EDGE / 8, 256>>>(ent, rel, src, dst, rid);
    k_scatter<<<N_EDGE / 8, 256>>>(ent, rel, src, dst, rid);

    int gblocks = (N_ENT + 127) / 128;   // 391
    k_gemm<<<gblocks, 256>>>(0, w_edge, out);
    k_gemm<<<gblocks, 256>>>(1, w_node, out);
    k_gemm<<<gblocks, 256>>>(2, w_comp, out);
}

// round 2
// speedup vs baseline: 1.1679x; 1.1679x over previous
#include <cuda_runtime.h>
#include <cuda_bf16.h>
#include <math.h>

#define N_ENT  50000
#define N_EDGE 500000
#define H      128

// -------- scratch (static __device__ — no allocation allowed) --------
__device__ float    g_neigh[3][N_ENT * H];  // normalized neighborhoods (76.8 MB)
__device__ int      g_deg[N_ENT];
__device__ int      g_off[N_ENT + 1];
__device__ int      g_cur[N_ENT];
__device__ unsigned g_pk[N_EDGE];           // packed src*512 + rel_id

__device__ __forceinline__ float dot4(float4 a, float4 b) {
    return a.x * b.x + a.y * b.y + a.z * b.z + a.w * b.w;
}
__device__ __forceinline__ float fast_tanh(float x) {
    float e = __expf(2.f * x);
    return 1.f - __fdividef(2.f, e + 1.f);
}

// -------- K0: copy ent -> out, zero degree histogram --------
__global__ void k_init(const float* __restrict__ ent, float* __restrict__ out) {
    int i = blockIdx.x * blockDim.x + threadIdx.x;   // covers N_ENT*H exactly
    out[i] = ent[i];
    if (i < N_ENT) g_deg[i] = 0;
}

// -------- K1: degree histogram --------
__global__ void k_hist(const int* __restrict__ dst) {
    int e = blockIdx.x * blockDim.x + threadIdx.x;
    if (e < N_EDGE) atomicAdd(&g_deg[dst[e]], 1);
}

// -------- K2: single-block exclusive scan -> offsets (+ cursor copy) --------
__global__ void k_scan() {
    __shared__ int part[1024];
    const int CH = (N_ENT + 1023) / 1024;            // 49
    int t = threadIdx.x;
    int begin = t * CH;
    int end   = begin + CH < N_ENT ? begin + CH : N_ENT;
    int s = 0;
    for (int i = begin; i < end; i++) s += g_deg[i];
    part[t] = s;
    __syncthreads();
    #pragma unroll
    for (int o = 1; o < 1024; o <<= 1) {
        int v = (t >= o) ? part[t - o] : 0;
        __syncthreads();
        part[t] += v;
        __syncthreads();
    }
    int run = (t == 0) ? 0 : part[t - 1];            // exclusive prefix
    for (int i = begin; i < end; i++) {
        g_off[i] = run;
        g_cur[i] = run;
        run += g_deg[i];
    }
    if (t == 1023) g_off[N_ENT] = run;               // = N_EDGE
}

// -------- K3: scatter edge payloads into dst-grouped lists --------
__global__ void k_fill(const int* __restrict__ src, const int* __restrict__ dst,
                       const int* __restrict__ rid) {
    int e = blockIdx.x * blockDim.x + threadIdx.x;
    if (e >= N_EDGE) return;
    int p = atomicAdd(&g_cur[dst[e]], 1);
    g_pk[p] = (unsigned)src[e] * 512u + (unsigned)rid[e];
}

// -------- K4: warp-per-node fused logits+softmax+aggregate (no atomics) ----
__global__ void __launch_bounds__(256)
k_agg(const float* __restrict__ ent, const float* __restrict__ rel) {
    int w    = (blockIdx.x * blockDim.x + threadIdx.x) >> 5;  // node id
    int lane = threadIdx.x & 31;
    if (w >= N_ENT) return;

    float4 v = ((const float4*)(ent + (size_t)w * H))[lane];  // key row, once
    int start = g_off[w], end = g_off[w + 1];

    float4 a0 = make_float4(0.f, 0.f, 0.f, 0.f), a1 = a0, a2 = a0;
    float s0 = 0.f, s1 = 0.f, s2 = 0.f;

    for (int i = start; i < end; i += 2) {                    // 2-edge chunks (MLP)
        unsigned pA = g_pk[i];
        int hasB    = (i + 1 < end);
        unsigned pB = g_pk[hasB ? i + 1 : i];

        float4 uA = ((const float4*)(ent + (size_t)(pA >> 9) * H))[lane];
        float4 qA = ((const float4*)(rel + (size_t)(pA & 511u) * H))[lane];
        float4 uB = ((const float4*)(ent + (size_t)(pB >> 9) * H))[lane];
        float4 qB = ((const float4*)(rel + (size_t)(pB & 511u) * H))[lane];

        float dnA = dot4(uA, v), deA = dot4(qA, v);
        float dnB = dot4(uB, v), deB = dot4(qB, v);
        #pragma unroll
        for (int o = 16; o; o >>= 1) {
            dnA += __shfl_xor_sync(0xffffffffu, dnA, o);
            deA += __shfl_xor_sync(0xffffffffu, deA, o);
            dnB += __shfl_xor_sync(0xffffffffu, dnB, o);
            deB += __shfl_xor_sync(0xffffffffu, deB, o);
        }
        // |logits| <~ 0.5 -> softmax without max-subtraction is exact
        float eA = __expf(deA), nA = __expf(dnA), cA = eA * nA;
        s0 += eA; s1 += nA; s2 += cA;
        a0.x += eA * qA.x; a0.y += eA * qA.y; a0.z += eA * qA.z; a0.w += eA * qA.w;
        a1.x += nA * uA.x; a1.y += nA * uA.y; a1.z += nA * uA.z; a1.w += nA * uA.w;
        a2.x += cA * (uA.x + qA.x); a2.y += cA * (uA.y + qA.y);
        a2.z += cA * (uA.z + qA.z); a2.w += cA * (uA.w + qA.w);
        if (hasB) {
            float eB = __expf(deB), nB = __expf(dnB), cB = eB * nB;
            s0 += eB; s1 += nB; s2 += cB;
            a0.x += eB * qB.x; a0.y += eB * qB.y; a0.z += eB * qB.z; a0.w += eB * qB.w;
            a1.x += nB * uB.x; a1.y += nB * uB.y; a1.z += nB * uB.z; a1.w += nB * uB.w;
            a2.x += cB * (uB.x + qB.x); a2.y += cB * (uB.y + qB.y);
            a2.z += cB * (uB.z + qB.z); a2.w += cB * (uB.w + qB.w);
        }
    }

    float i0 = (end > start) ? 1.f / s0 : 0.f;
    float i1 = (end > start) ? 1.f / s1 : 0.f;
    float i2 = (end > start) ? 1.f / s2 : 0.f;
    size_t off = (size_t)w * H + lane * 4;
    *(float4*)&g_neigh[0][off] = make_float4(a0.x * i0, a0.y * i0, a0.z * i0, a0.w * i0);
    *(float4*)&g_neigh[1][off] = make_float4(a1.x * i1, a1.y * i1, a1.z * i1, a1.w * i1);
    *(float4*)&g_neigh[2][off] = make_float4(a2.x * i2, a2.y * i2, a2.z * i2, a2.w * i2);
}

// -------- K5: out += tanh(neigh @ W), one launch per layer --------
__global__ void __launch_bounds__(256, 2)
k_gemm(int layer, const float* __restrict__ W, float* __restrict__ out) {
    const float* neigh = g_neigh[layer];
    __shared__ float sN[128][16];
    __shared__ float sW[16][128];

    int tx = threadIdx.x & 15;
    int ty = threadIdx.x >> 4;
    int row0 = blockIdx.x * 128;

    float acc[8][8];
    #pragma unroll
    for (int i = 0; i < 8; i++)
        #pragma unroll
        for (int j = 0; j < 8; j++) acc[i][j] = 0.0f;

    for (int k0 = 0; k0 < H; k0 += 16) {
        int t = threadIdx.x;
        #pragma unroll
        for (int i = 0; i < 2; i++) {
            int idx = t + i * 256;
            int n   = idx >> 2;
            int kq  = (idx & 3) * 4;
            float4 val = (row0 + n < N_ENT)
                ? *(const float4*)(neigh + (size_t)(row0 + n) * H + k0 + kq)
                : make_float4(0.f, 0.f, 0.f, 0.f);
            *(float4*)&sN[n][kq] = val;
        }
        #pragma unroll
        for (int i = 0; i < 2; i++) {
            int idx = t + i * 256;
            int kk  = idx >> 5;
            int h4  = (idx & 31) * 4;
            *(float4*)&sW[kk][h4] = *(const float4*)(W + (size_t)(k0 + kk) * H + h4);
        }
        __syncthreads();
        #pragma unroll
        for (int kk = 0; kk < 16; kk++) {
            float a[8], b[8];
            #pragma unroll
            for (int i = 0; i < 8; i++) a[i] = sN[ty * 8 + i][kk];
            float4 b0 = *(float4*)&sW[kk][tx * 8];
            float4 b1 = *(float4*)&sW[kk][tx * 8 + 4];
            b[0]=b0.x; b[1]=b0.y; b[2]=b0.z; b[3]=b0.w;
            b[4]=b1.x; b[5]=b1.y; b[6]=b1.z; b[7]=b1.w;
            #pragma unroll
            for (int i = 0; i < 8; i++)
                #pragma unroll
                for (int j = 0; j < 8; j++) acc[i][j] += a[i] * b[j];
        }
        __syncthreads();
    }

    #pragma unroll
    for (int i = 0; i < 8; i++) {
        int n = row0 + ty * 8 + i;
        if (n < N_ENT) {
            #pragma unroll
            for (int j = 0; j < 8; j++)
                out[(size_t)n * H + tx * 8 + j] += fast_tanh(acc[i][j]);
        }
    }
}

extern "C" void kernel_launch(void* const* d_in, const int* in_sizes, int n_in,
                              void* d_out, int out_size) {
    const float* ent    = (const float*)d_in[0];
    const float* rel    = (const float*)d_in[1];
    const float* w_edge = (const float*)d_in[2];
    const float* w_node = (const float*)d_in[3];
    const float* w_comp = (const float*)d_in[4];
    const int*   src    = (const int*)d_in[5];
    const int*   dst    = (const int*)d_in[6];
    const int*   rid    = (const int*)d_in[7];
    float*       out    = (float*)d_out;

    k_init<<<(N_ENT * H) / 256, 256>>>(ent, out);          // 6.4M = 25000*256
    k_hist<<<(N_EDGE + 255) / 256, 256>>>(dst);
    k_scan<<<1, 1024>>>();
    k_fill<<<(N_EDGE + 255) / 256, 256>>>(src, dst, rid);
    k_agg <<<N_ENT / 8, 256>>>(ent, rel);                  // 6250 blocks, warp/node

    int gblocks = (N_ENT + 127) / 128;                     // 391
    k_gemm<<<gblocks, 256>>>(0, w_edge, out);
    k_gemm<<<gblocks, 256>>>(1, w_node, out);
    k_gemm<<<gblocks, 256>>>(2, w_comp, out);
}

// round 4
// speedup vs baseline: 1.4140x; 1.2107x over previous
#include <cuda_runtime.h>
#include <cuda_bf16.h>
#include <math.h>
#include <stdint.h>

#define N_ENT  50000
#define N_PAD  50048           // 391 * 128
#define N_EDGE 500000
#define H      128

// ================= scratch (static __device__) =================
__device__ int      g_deg[N_ENT];
__device__ int      g_off[N_ENT + 1];
__device__ int      g_cur[N_ENT];
__device__ unsigned g_pk[N_EDGE];                            // packed src*512 + rel_id
__device__ __align__(16) __nv_bfloat16 g_ahi[3][N_PAD * H];  // neigh hi (bf16)
__device__ __align__(16) __nv_bfloat16 g_alo[3][N_PAD * H];  // neigh lo (bf16)
__device__ __align__(16) __nv_bfloat16 g_wthi[3][H * H];     // W^T hi (h-major rows)
__device__ __align__(16) __nv_bfloat16 g_wtlo[3][H * H];     // W^T lo

// ================= helpers =================
__device__ __forceinline__ float dot4(float4 a, float4 b) {
    return a.x * b.x + a.y * b.y + a.z * b.z + a.w * b.w;
}
__device__ __forceinline__ float fast_tanh(float x) {
    float e = __expf(2.f * x);
    return 1.f - __fdividef(2.f, e + 1.f);
}
__device__ __forceinline__ uint32_t smem_u32(const void* p) {
    uint32_t a;
    asm("{ .reg .u64 t; cvta.to.shared.u64 t, %1; cvt.u32.u64 %0, t; }" : "=r"(a) : "l"(p));
    return a;
}
#define LDSM4(R0, R1, R2, R3, addr) \
    asm volatile("ldmatrix.sync.aligned.m8n8.x4.shared.b16 {%0,%1,%2,%3}, [%4];" \
        : "=r"(R0), "=r"(R1), "=r"(R2), "=r"(R3) : "r"(addr))
#define MMA16816(C, A0, A1, A2, A3, B0, B1) \
    asm volatile("mma.sync.aligned.m16n8k16.row.col.f32.bf16.bf16.f32 " \
        "{%0,%1,%2,%3}, {%4,%5,%6,%7}, {%8,%9}, {%0,%1,%2,%3};" \
        : "+f"((C)[0]), "+f"((C)[1]), "+f"((C)[2]), "+f"((C)[3]) \
        : "r"(A0), "r"(A1), "r"(A2), "r"(A3), "r"(B0), "r"(B1))

// ================= K0: copy ent -> out, zero degree, zero A-pad rows ======
__global__ void k_init(const float* __restrict__ ent, float* __restrict__ out) {
    int i = blockIdx.x * blockDim.x + threadIdx.x;
    out[i] = ent[i];
    if (i < N_ENT) g_deg[i] = 0;
    if (i < 3 * (N_PAD - N_ENT) * H) {                       // 18432 pad elems
        int l = i / ((N_PAD - N_ENT) * H);
        int r = i % ((N_PAD - N_ENT) * H);
        g_ahi[l][N_ENT * H + r] = __float2bfloat16(0.f);
        g_alo[l][N_ENT * H + r] = __float2bfloat16(0.f);
    }
}

// ================= K1: degree histogram =================
__global__ void k_hist(const int* __restrict__ dst) {
    int e = blockIdx.x * blockDim.x + threadIdx.x;
    if (e < N_EDGE) atomicAdd(&g_deg[dst[e]], 1);
}

// ================= K2: single-block exclusive scan =================
__global__ void k_scan() {
    __shared__ int part[1024];
    const int CH = (N_ENT + 1023) / 1024;
    int t = threadIdx.x;
    int begin = t * CH;
    int end = begin + CH < N_ENT ? begin + CH : N_ENT;
    int s = 0;
    for (int i = begin; i < end; i++) s += g_deg[i];
    part[t] = s;
    __syncthreads();
    #pragma unroll
    for (int o = 1; o < 1024; o <<= 1) {
        int v = (t >= o) ? part[t - o] : 0;
        __syncthreads();
        part[t] += v;
        __syncthreads();
    }
    int run = (t == 0) ? 0 : part[t - 1];
    for (int i = begin; i < end; i++) {
        g_off[i] = run;
        g_cur[i] = run;
        run += g_deg[i];
    }
    if (t == 1023) g_off[N_ENT] = run;
}

// ================= K3: dst-grouped edge lists =================
__global__ void k_fill(const int* __restrict__ src, const int* __restrict__ dst,
                       const int* __restrict__ rid) {
    int e = blockIdx.x * blockDim.x + threadIdx.x;
    if (e >= N_EDGE) return;
    int p = atomicAdd(&g_cur[dst[e]], 1);
    g_pk[p] = (unsigned)src[e] * 512u + (unsigned)rid[e];
}

// ================= K4: W^T + bf16 hi/lo split =================
__global__ void k_wprep(const float* __restrict__ we, const float* __restrict__ wn,
                        const float* __restrict__ wc) {
    int i = blockIdx.x * blockDim.x + threadIdx.x;   // 3*16384
    int l = i >> 14, r = i & 16383;
    int k = r >> 7, h = r & 127;
    const float* W = (l == 0) ? we : (l == 1) ? wn : wc;
    float x = W[k * H + h];
    __nv_bfloat16 hi = __float2bfloat16(x);
    g_wthi[l][h * H + k] = hi;
    g_wtlo[l][h * H + k] = __float2bfloat16(x - __bfloat162float(hi));
}

// ================= K5: warp-per-node fused agg + bf16 split-out ==========
__device__ __forceinline__ void split_store4(__nv_bfloat16* hip, __nv_bfloat16* lop,
                                             float a, float b, float c, float d) {
    __nv_bfloat162 h01 = __floats2bfloat162_rn(a, b);
    __nv_bfloat162 h23 = __floats2bfloat162_rn(c, d);
    __nv_bfloat162 l01 = __floats2bfloat162_rn(a - __bfloat162float(h01.x),
                                               b - __bfloat162float(h01.y));
    __nv_bfloat162 l23 = __floats2bfloat162_rn(c - __bfloat162float(h23.x),
                                               d - __bfloat162float(h23.y));
    *(__nv_bfloat162*)(hip)     = h01;
    *(__nv_bfloat162*)(hip + 2) = h23;
    *(__nv_bfloat162*)(lop)     = l01;
    *(__nv_bfloat162*)(lop + 2) = l23;
}

__global__ void __launch_bounds__(256)
k_agg(const float* __restrict__ ent, const float* __restrict__ rel) {
    int w    = (blockIdx.x * blockDim.x + threadIdx.x) >> 5;
    int lane = threadIdx.x & 31;
    if (w >= N_ENT) return;

    float4 v = ((const float4*)(ent + (size_t)w * H))[lane];
    int start = g_off[w], end = g_off[w + 1];

    float4 a0 = make_float4(0.f, 0.f, 0.f, 0.f), a1 = a0, a2 = a0;
    float s0 = 0.f, s1 = 0.f, s2 = 0.f;

    for (int i = start; i < end; i += 2) {
        unsigned pA = g_pk[i];
        int hasB    = (i + 1 < end);
        unsigned pB = g_pk[hasB ? i + 1 : i];

        float4 uA = ((const float4*)(ent + (size_t)(pA >> 9) * H))[lane];
        float4 qA = ((const float4*)(rel + (size_t)(pA & 511u) * H))[lane];
        float4 uB = ((const float4*)(ent + (size_t)(pB >> 9) * H))[lane];
        float4 qB = ((const float4*)(rel + (size_t)(pB & 511u) * H))[lane];

        float dnA = dot4(uA, v), deA = dot4(qA, v);
        float dnB = dot4(uB, v), deB = dot4(qB, v);
        #pragma unroll
        for (int o = 16; o; o >>= 1) {
            dnA += __shfl_xor_sync(0xffffffffu, dnA, o);
            deA += __shfl_xor_sync(0xffffffffu, deA, o);
            dnB += __shfl_xor_sync(0xffffffffu, dnB, o);
            deB += __shfl_xor_sync(0xffffffffu, deB, o);
        }
        float eA = __expf(deA), nA = __expf(dnA), cA = eA * nA;
        s0 += eA; s1 += nA; s2 += cA;
        a0.x += eA * qA.x; a0.y += eA * qA.y; a0.z += eA * qA.z; a0.w += eA * qA.w;
        a1.x += nA * uA.x; a1.y += nA * uA.y; a1.z += nA * uA.z; a1.w += nA * uA.w;
        a2.x += cA * (uA.x + qA.x); a2.y += cA * (uA.y + qA.y);
        a2.z += cA * (uA.z + qA.z); a2.w += cA * (uA.w + qA.w);
        if (hasB) {
            float eB = __expf(deB), nB = __expf(dnB), cB = eB * nB;
            s0 += eB; s1 += nB; s2 += cB;
            a0.x += eB * qB.x; a0.y += eB * qB.y; a0.z += eB * qB.z; a0.w += eB * qB.w;
            a1.x += nB * uB.x; a1.y += nB * uB.y; a1.z += nB * uB.z; a1.w += nB * uB.w;
            a2.x += cB * (uB.x + qB.x); a2.y += cB * (uB.y + qB.y);
            a2.z += cB * (uB.z + qB.z); a2.w += cB * (uB.w + qB.w);
        }
    }

    float i0 = (end > start) ? 1.f / s0 : 0.f;
    float i1 = (end > start) ? 1.f / s1 : 0.f;
    float i2 = (end > start) ? 1.f / s2 : 0.f;
    size_t off = (size_t)w * H + lane * 4;
    split_store4(&g_ahi[0][off], &g_alo[0][off], a0.x * i0, a0.y * i0, a0.z * i0, a0.w * i0);
    split_store4(&g_ahi[1][off], &g_alo[1][off], a1.x * i1, a1.y * i1, a1.z * i1, a1.w * i1);
    split_store4(&g_ahi[2][off], &g_alo[2][off], a2.x * i2, a2.y * i2, a2.z * i2, a2.w * i2);
}

// ================= K6: HMMA split-bf16 GEMM, all 3 layers per CTA =========
// smem: 4 tiles of 128 rows x 272B pitch (A hi, A lo, W^T hi, W^T lo)
#define PITCH    272
#define TILE_B   (128 * PITCH)          // 34816
#define SM_AH    0
#define SM_AL    TILE_B
#define SM_WH    (2 * TILE_B)
#define SM_WL    (3 * TILE_B)
#define SM_TOT   (4 * TILE_B)           // 139264

__global__ void __launch_bounds__(256, 1)
k_gemm3(float* __restrict__ out) {
    extern __shared__ char sm[];
    uint32_t sb = smem_u32(sm);
    int tid  = threadIdx.x;
    int wid  = tid >> 5;
    int lane = tid & 31;
    int row0 = blockIdx.x * 128;

    // lane-dependent ldmatrix base offsets (q = lane>>3, r = lane&7)
    int q = lane >> 3, r = lane & 7;
    uint32_t a_off = (uint32_t)((wid * 16 + r + (q & 1) * 8) * PITCH + (q >> 1) * 16);
    uint32_t b_off = (uint32_t)(((q >> 1) * 8 + r) * PITCH + (q & 1) * 16);

    for (int layer = 0; layer < 3; layer++) {
        // ---- fill 4 tiles (each 128 rows x 16 uint4) ----
        const uint4* srcs[4] = {
            (const uint4*)(g_ahi[layer] + (size_t)row0 * H),
            (const uint4*)(g_alo[layer] + (size_t)row0 * H),
            (const uint4*)(g_wthi[layer]),
            (const uint4*)(g_wtlo[layer]) };
        #pragma unroll
        for (int t = 0; t < 4; t++) {
            char* base = sm + t * TILE_B;
            #pragma unroll
            for (int i = 0; i < 8; i++) {
                int idx = i * 256 + tid;          // 0..2047
                int row = idx >> 4;
                int ch  = idx & 15;
                *(uint4*)(base + row * PITCH + ch * 16) = srcs[t][row * 16 + ch];
            }
        }
        __syncthreads();

        // ---- compute: 3 passes (AhBh, AhBl, AlBh) into fp32 acc ----
        float c[16][4];
        #pragma unroll
        for (int nt = 0; nt < 16; nt++)
            #pragma unroll
            for (int j = 0; j < 4; j++) c[nt][j] = 0.f;

        #pragma unroll
        for (int pass = 0; pass < 3; pass++) {
            uint32_t ab = sb + (pass == 2 ? SM_AL : SM_AH) + a_off;
            uint32_t bb = sb + (pass == 1 ? SM_WL : SM_WH) + b_off;
            #pragma unroll
            for (int ks = 0; ks < 8; ks++) {
                uint32_t aa0, aa1, aa2, aa3;
                LDSM4(aa0, aa1, aa2, aa3, ab + ks * 32);
                #pragma unroll
                for (int np = 0; np < 8; np++) {
                    uint32_t b0, b1, b2, b3;
                    LDSM4(b0, b1, b2, b3, bb + np * (16 * PITCH) + ks * 32);
                    MMA16816(c[np * 2],     aa0, aa1, aa2, aa3, b0, b1);
                    MMA16816(c[np * 2 + 1], aa0, aa1, aa2, aa3, b2, b3);
                }
            }
        }

        // ---- epilogue: out += tanh(c) (block owns its rows; no race) ----
        int m0 = row0 + wid * 16 + (lane >> 2);
        int nb = (lane & 3) * 2;
        #pragma unroll
        for (int nt = 0; nt < 16; nt++) {
            int n = nt * 8 + nb;
            if (m0 < N_ENT) {
                float2* p = (float2*)(out + (size_t)m0 * H + n);
                float2 v0 = *p;
                v0.x += fast_tanh(c[nt][0]);
                v0.y += fast_tanh(c[nt][1]);
                *p = v0;
            }
            if (m0 + 8 < N_ENT) {
                float2* p = (float2*)(out + (size_t)(m0 + 8) * H + n);
                float2 v1 = *p;
                v1.x += fast_tanh(c[nt][2]);
                v1.y += fast_tanh(c[nt][3]);
                *p = v1;
            }
        }
        __syncthreads();    // before next layer overwrites smem
    }
}

// ================= launch =================
extern "C" void kernel_launch(void* const* d_in, const int* in_sizes, int n_in,
                              void* d_out, int out_size) {
    const float* ent    = (const float*)d_in[0];
    const float* rel    = (const float*)d_in[1];
    const float* w_edge = (const float*)d_in[2];
    const float* w_node = (const float*)d_in[3];
    const float* w_comp = (const float*)d_in[4];
    const int*   src    = (const int*)d_in[5];
    const int*   dst    = (const int*)d_in[6];
    const int*   rid    = (const int*)d_in[7];
    float*       out    = (float*)d_out;

    static int smem_set = 0;
    if (!smem_set) {
        cudaFuncSetAttribute(k_gemm3, cudaFuncAttributeMaxDynamicSharedMemorySize, SM_TOT);
        smem_set = 1;
    }

    k_init <<<(N_ENT * H) / 256, 256>>>(ent, out);
    k_hist <<<(N_EDGE + 255) / 256, 256>>>(dst);
    k_scan <<<1, 1024>>>();
    k_fill <<<(N_EDGE + 255) / 256, 256>>>(src, dst, rid);
    k_wprep<<<(3 * H * H) / 256, 256>>>(w_edge, w_node, w_comp);
    k_agg  <<<N_ENT / 8, 256>>>(ent, rel);

    k_gemm3<<<N_PAD / 128, 256, SM_TOT>>>(out);   // 391 CTAs, 3 layers each
}